// round 4
// baseline (speedup 1.0000x reference)
#include <cuda_runtime.h>
#include <cuda_bf16.h>

// Accumulators: [0]=sum focal aspect, [1]=sum focal opinion, [2]=sum bce,
//               [3]=count valid aspect, [4]=count valid opinion
__device__ double g_acc[5];

__global__ void init_acc_kernel() {
    if (threadIdx.x < 5) g_acc[threadIdx.x] = 0.0;
}

__device__ __forceinline__ float focal3(float x0, float x1, float x2, int lab, float& cnt) {
    if (lab == -100) return 0.0f;
    float m = fmaxf(x0, fmaxf(x1, x2));
    float lse = m + __logf(__expf(x0 - m) + __expf(x1 - m) + __expf(x2 - m));
    float xl = (lab == 0) ? x0 : ((lab == 1) ? x1 : x2);
    float ce = lse - xl;
    float pt = __expf(-ce);
    float u = 1.0f - pt;
    cnt += 1.0f;
    return u * u * ce;
}

__device__ __forceinline__ float bce1(float z, float y) {
    return fmaxf(z, 0.0f) - z * y + log1pf(__expf(-fabsf(z)));
}

__global__ void __launch_bounds__(256)
main_loss_kernel(const float* __restrict__ al, const float* __restrict__ ol,
                 const float* __restrict__ bl,
                 const int* __restrict__ la, const int* __restrict__ lo,
                 int total, int S) {
    int idx = blockIdx.x * blockDim.x + threadIdx.x;
    float v0 = 0.f, v1 = 0.f, v2 = 0.f, v3 = 0.f, v4 = 0.f;
    if (idx < total) {
        int s = idx - (idx / S) * S;
        int lab_a = la[idx];
        int lab_o = lo[idx];

        const float* ap = al + 3 * idx;
        v0 = focal3(ap[0], ap[1], ap[2], lab_a, v3);
        const float* op = ol + 3 * idx;
        v1 = focal3(op[0], op[1], op[2], lab_o, v4);

        // boundary labels: start = (lab==1); end = (lab==2 && next!=2)
        int na = (s == S - 1) ? -1 : la[idx + 1];
        int no = (s == S - 1) ? -1 : lo[idx + 1];
        float y0 = ((lab_a == 1) | (lab_o == 1)) ? 1.0f : 0.0f;
        float y1 = (((lab_a == 2) & (na != 2)) | ((lab_o == 2) & (no != 2))) ? 1.0f : 0.0f;
        float2 z = *reinterpret_cast<const float2*>(bl + 2 * (size_t)idx);
        v2 = bce1(z.x, y0) + bce1(z.y, y1);
    }

    // warp reduce
    #pragma unroll
    for (int off = 16; off; off >>= 1) {
        v0 += __shfl_down_sync(0xffffffffu, v0, off);
        v1 += __shfl_down_sync(0xffffffffu, v1, off);
        v2 += __shfl_down_sync(0xffffffffu, v2, off);
        v3 += __shfl_down_sync(0xffffffffu, v3, off);
        v4 += __shfl_down_sync(0xffffffffu, v4, off);
    }

    __shared__ float sacc[5];
    if (threadIdx.x < 5) sacc[threadIdx.x] = 0.0f;
    __syncthreads();
    if ((threadIdx.x & 31) == 0) {
        atomicAdd(&sacc[0], v0);
        atomicAdd(&sacc[1], v1);
        atomicAdd(&sacc[2], v2);
        atomicAdd(&sacc[3], v3);
        atomicAdd(&sacc[4], v4);
    }
    __syncthreads();
    if (threadIdx.x == 0) {
        atomicAdd(&g_acc[0], (double)sacc[0]);
        atomicAdd(&g_acc[1], (double)sacc[1]);
        atomicAdd(&g_acc[2], (double)sacc[2]);
        atomicAdd(&g_acc[3], (double)sacc[3]);
        atomicAdd(&g_acc[4], (double)sacc[4]);
    }
}

__global__ void __launch_bounds__(256)
finalize_kernel(const float* __restrict__ sl, const int* __restrict__ ls,
                float* __restrict__ out, int Bn, int total) {
    float ce = 0.f, val = 0.f;
    for (int b = threadIdx.x; b < Bn; b += blockDim.x) {
        int lab = ls[b];
        if (lab != -100) {
            float x0 = sl[3 * b], x1 = sl[3 * b + 1], x2 = sl[3 * b + 2];
            float m = fmaxf(x0, fmaxf(x1, x2));
            float lse = m + __logf(__expf(x0 - m) + __expf(x1 - m) + __expf(x2 - m));
            float xl = (lab == 0) ? x0 : ((lab == 1) ? x1 : x2);
            ce += lse - xl;
            val += 1.0f;
        }
    }
    #pragma unroll
    for (int off = 16; off; off >>= 1) {
        ce  += __shfl_down_sync(0xffffffffu, ce, off);
        val += __shfl_down_sync(0xffffffffu, val, off);
    }
    __shared__ float sc[2];
    if (threadIdx.x < 2) sc[threadIdx.x] = 0.0f;
    __syncthreads();
    if ((threadIdx.x & 31) == 0) {
        atomicAdd(&sc[0], ce);
        atomicAdd(&sc[1], val);
    }
    __syncthreads();
    if (threadIdx.x == 0) {
        double fa = (g_acc[3] > 0.0) ? g_acc[0] / fmax(g_acc[3], 1.0) : 0.0;
        double fo = (g_acc[4] > 0.0) ? g_acc[1] / fmax(g_acc[4], 1.0) : 0.0;
        double sent = (double)sc[0] / fmax((double)sc[1], 1.0);
        double bnd = g_acc[2] / ((double)total * 2.0);
        out[0] = (float)(fa + fo + sent + 0.5 * bnd);
    }
}

extern "C" void kernel_launch(void* const* d_in, const int* in_sizes, int n_in,
                              void* d_out, int out_size) {
    const float* aspect_logits    = (const float*)d_in[0];
    const float* opinion_logits   = (const float*)d_in[1];
    const float* sentiment_logits = (const float*)d_in[2];
    const float* boundary_logits  = (const float*)d_in[3];
    const int*   aspect_labels    = (const int*)d_in[4];
    const int*   opinion_labels   = (const int*)d_in[5];
    const int*   sentiment_labels = (const int*)d_in[6];
    float* out = (float*)d_out;

    int B = in_sizes[2] / 3;        // sentiment_logits = B*3
    int total = in_sizes[4];        // aspect_labels = B*S
    int S = total / B;

    init_acc_kernel<<<1, 32>>>();
    int threads = 256;
    int blocks = (total + threads - 1) / threads;
    main_loss_kernel<<<blocks, threads>>>(aspect_logits, opinion_logits,
                                          boundary_logits, aspect_labels,
                                          opinion_labels, total, S);
    finalize_kernel<<<1, 256>>>(sentiment_logits, sentiment_labels, out, B, total);
}

// round 5
// speedup vs baseline: 2.5154x; 2.5154x over previous
#include <cuda_runtime.h>
#include <cuda_bf16.h>

#define MAXB 8192
// per-block partials: [b*5+0]=focal_aspect, +1=focal_opinion, +2=bce_sum,
//                     +3=valid_aspect_cnt, +4=valid_opinion_cnt
__device__ float g_part[MAXB * 5];

__device__ __forceinline__ float focal3(float x0, float x1, float x2, int lab, float& cnt) {
    if (lab == -100) return 0.0f;
    float m  = fmaxf(x0, fmaxf(x1, x2));
    float e0 = __expf(x0 - m), e1 = __expf(x1 - m), e2 = __expf(x2 - m);
    float sum = e0 + e1 + e2;
    float xl = (lab == 0) ? x0 : ((lab == 1) ? x1 : x2);
    float el = (lab == 0) ? e0 : ((lab == 1) ? e1 : e2);
    float ce = __logf(sum) - (xl - m);
    float pt = el / sum;           // == exp(-ce), reuses the exponentials
    float u  = 1.0f - pt;
    cnt += 1.0f;
    return u * u * ce;
}

__device__ __forceinline__ float bce1(float z, float y) {
    return fmaxf(z, 0.0f) - z * y + __logf(1.0f + __expf(-fabsf(z)));
}

__global__ void __launch_bounds__(256)
main_loss_kernel(const float* __restrict__ al, const float* __restrict__ ol,
                 const float* __restrict__ bl,
                 const int* __restrict__ la, const int* __restrict__ lo,
                 int total4, int S) {
    int t = blockIdx.x * blockDim.x + threadIdx.x;
    float v0 = 0.f, v1 = 0.f, v2 = 0.f, v3 = 0.f, v4 = 0.f;

    if (t < total4) {
        int base = t * 4;

        int4 A4 = reinterpret_cast<const int4*>(la)[t];
        int4 O4 = reinterpret_cast<const int4*>(lo)[t];
        int labA[4] = {A4.x, A4.y, A4.z, A4.w};
        int labO[4] = {O4.x, O4.y, O4.z, O4.w};

        // next-label for the last element of this 4-group
        int s3 = base - (base / S) * S + 3;   // position of element 3 within row
        int nA3, nO3;
        if (s3 == S - 1) { nA3 = -1; nO3 = -1; }
        else             { nA3 = la[base + 4]; nO3 = lo[base + 4]; }
        int nxtA[4] = {labA[1], labA[2], labA[3], nA3};
        int nxtO[4] = {labO[1], labO[2], labO[3], nO3};

        // aspect logits: 12 floats = 3x float4
        const float4* ap = reinterpret_cast<const float4*>(al) + (size_t)t * 3;
        float4 a0 = ap[0], a1 = ap[1], a2 = ap[2];
        float ax[12] = {a0.x, a0.y, a0.z, a0.w, a1.x, a1.y, a1.z, a1.w,
                        a2.x, a2.y, a2.z, a2.w};

        const float4* op = reinterpret_cast<const float4*>(ol) + (size_t)t * 3;
        float4 b0 = op[0], b1 = op[1], b2 = op[2];
        float ox[12] = {b0.x, b0.y, b0.z, b0.w, b1.x, b1.y, b1.z, b1.w,
                        b2.x, b2.y, b2.z, b2.w};

        // boundary logits: 8 floats = 2x float4
        const float4* bp = reinterpret_cast<const float4*>(bl) + (size_t)t * 2;
        float4 z0 = bp[0], z1 = bp[1];
        float zz[8] = {z0.x, z0.y, z0.z, z0.w, z1.x, z1.y, z1.z, z1.w};

        #pragma unroll
        for (int p = 0; p < 4; p++) {
            v0 += focal3(ax[3*p], ax[3*p+1], ax[3*p+2], labA[p], v3);
            v1 += focal3(ox[3*p], ox[3*p+1], ox[3*p+2], labO[p], v4);
            float y0 = ((labA[p] == 1) | (labO[p] == 1)) ? 1.0f : 0.0f;
            float y1 = (((labA[p] == 2) & (nxtA[p] != 2)) |
                        ((labO[p] == 2) & (nxtO[p] != 2))) ? 1.0f : 0.0f;
            v2 += bce1(zz[2*p], y0) + bce1(zz[2*p+1], y1);
        }
    }

    // warp reduce
    #pragma unroll
    for (int off = 16; off; off >>= 1) {
        v0 += __shfl_down_sync(0xffffffffu, v0, off);
        v1 += __shfl_down_sync(0xffffffffu, v1, off);
        v2 += __shfl_down_sync(0xffffffffu, v2, off);
        v3 += __shfl_down_sync(0xffffffffu, v3, off);
        v4 += __shfl_down_sync(0xffffffffu, v4, off);
    }

    // deterministic block reduce: 8 warps -> shared -> warp 0
    __shared__ float sw[8][5];
    int wid = threadIdx.x >> 5;
    if ((threadIdx.x & 31) == 0) {
        sw[wid][0] = v0; sw[wid][1] = v1; sw[wid][2] = v2;
        sw[wid][3] = v3; sw[wid][4] = v4;
    }
    __syncthreads();
    if (threadIdx.x == 0) {
        float s0 = 0.f, s1 = 0.f, s2 = 0.f, s3 = 0.f, s4 = 0.f;
        #pragma unroll
        for (int w = 0; w < 8; w++) {
            s0 += sw[w][0]; s1 += sw[w][1]; s2 += sw[w][2];
            s3 += sw[w][3]; s4 += sw[w][4];
        }
        float* dst = &g_part[(size_t)blockIdx.x * 5];
        dst[0] = s0; dst[1] = s1; dst[2] = s2; dst[3] = s3; dst[4] = s4;
    }
}

__global__ void __launch_bounds__(256)
finalize_kernel(const float* __restrict__ sl, const int* __restrict__ ls,
                float* __restrict__ out, int Bn, int total, int nblocks) {
    // accumulate per-block partials in double
    double d0 = 0.0, d1 = 0.0, d2 = 0.0, d3 = 0.0, d4 = 0.0;
    for (int b = threadIdx.x; b < nblocks; b += blockDim.x) {
        const float* p = &g_part[(size_t)b * 5];
        d0 += (double)p[0]; d1 += (double)p[1]; d2 += (double)p[2];
        d3 += (double)p[3]; d4 += (double)p[4];
    }
    // sentiment CE
    float ce = 0.f, val = 0.f;
    for (int b = threadIdx.x; b < Bn; b += blockDim.x) {
        int lab = ls[b];
        if (lab != -100) {
            float x0 = sl[3*b], x1 = sl[3*b+1], x2 = sl[3*b+2];
            float m = fmaxf(x0, fmaxf(x1, x2));
            float lse = m + __logf(__expf(x0-m) + __expf(x1-m) + __expf(x2-m));
            float xl = (lab == 0) ? x0 : ((lab == 1) ? x1 : x2);
            ce += lse - xl;
            val += 1.0f;
        }
    }
    #pragma unroll
    for (int off = 16; off; off >>= 1) {
        d0 += __shfl_down_sync(0xffffffffu, d0, off);
        d1 += __shfl_down_sync(0xffffffffu, d1, off);
        d2 += __shfl_down_sync(0xffffffffu, d2, off);
        d3 += __shfl_down_sync(0xffffffffu, d3, off);
        d4 += __shfl_down_sync(0xffffffffu, d4, off);
        ce  += __shfl_down_sync(0xffffffffu, ce, off);
        val += __shfl_down_sync(0xffffffffu, val, off);
    }
    __shared__ double sd[8][5];
    __shared__ float sf[8][2];
    int wid = threadIdx.x >> 5;
    if ((threadIdx.x & 31) == 0) {
        sd[wid][0] = d0; sd[wid][1] = d1; sd[wid][2] = d2;
        sd[wid][3] = d3; sd[wid][4] = d4;
        sf[wid][0] = ce; sf[wid][1] = val;
    }
    __syncthreads();
    if (threadIdx.x == 0) {
        double t0 = 0, t1 = 0, t2 = 0, t3 = 0, t4 = 0, tce = 0, tva = 0;
        #pragma unroll
        for (int w = 0; w < 8; w++) {
            t0 += sd[w][0]; t1 += sd[w][1]; t2 += sd[w][2];
            t3 += sd[w][3]; t4 += sd[w][4];
            tce += (double)sf[w][0]; tva += (double)sf[w][1];
        }
        double fa   = (t3 > 0.0) ? t0 / fmax(t3, 1.0) : 0.0;
        double fo   = (t4 > 0.0) ? t1 / fmax(t4, 1.0) : 0.0;
        double sent = tce / fmax(tva, 1.0);
        double bnd  = t2 / ((double)total * 2.0);
        out[0] = (float)(fa + fo + sent + 0.5 * bnd);
    }
}

extern "C" void kernel_launch(void* const* d_in, const int* in_sizes, int n_in,
                              void* d_out, int out_size) {
    const float* aspect_logits    = (const float*)d_in[0];
    const float* opinion_logits   = (const float*)d_in[1];
    const float* sentiment_logits = (const float*)d_in[2];
    const float* boundary_logits  = (const float*)d_in[3];
    const int*   aspect_labels    = (const int*)d_in[4];
    const int*   opinion_labels   = (const int*)d_in[5];
    const int*   sentiment_labels = (const int*)d_in[6];
    float* out = (float*)d_out;

    int B = in_sizes[2] / 3;       // sentiment_logits = B*3
    int total = in_sizes[4];       // aspect_labels = B*S
    int S = total / B;

    int total4  = total / 4;       // total is divisible by 4 (B*S = 2^21)
    int threads = 256;
    int blocks  = (total4 + threads - 1) / threads;   // 2048 for B=256,S=8192

    main_loss_kernel<<<blocks, threads>>>(aspect_logits, opinion_logits,
                                          boundary_logits, aspect_labels,
                                          opinion_labels, total4, S);
    finalize_kernel<<<1, 256>>>(sentiment_logits, sentiment_labels, out,
                                B, total, blocks);
}